// round 13
// baseline (speedup 1.0000x reference)
#include <cuda_runtime.h>

// LUT tree, monomial-coefficient form (R12 structure; G=2, 3 CTAs/SM).
// Loader Mobius-transforms tables -> node eval is 15 pure FMAs.
// Persistent warps steal 2-row tiles. Layer-0 x loads prefetched THREE batches
// ahead through a depth-4 register ring (B[4][2] = 32 regs -> fits the 85-reg
// cap for 3 CTAs/SM without spills; phase stable: 8 batches % 4 == 0).
// Next tile stolen at j==5; its batches 0..2 load under j=5..7 + tail layers.
// Tail layers are table-outer/rows-inner (coefs loaded once, reused over G).

#define THREADS  256
#define NWARPS   8
#define GRID     444            // 3 CTAs/SM * 148 SMs
#define G        2              // rows per tile (32768 % 2 == 0, no guards)

#define NODE_F   20             // 16 coefs + 4 pad -> 80B stride, conflict-free
#define N_NODES  341            // 256+64+16+4+1, by global node id g
#define TTOT     (N_NODES * NODE_F)
#define XCHF     (NWARPS * G * 256)
#define SMEM_B   ((TTOT + XCHF) * 4)   // 27280 + 16384 = 43664 B

typedef unsigned uns;
__device__ uns g_ctr;
__global__ void reset_ctr() { g_ctr = 0; }

// eval with monomial coefs in registers; index = b0+2b1+4b2+8b3 (bit i <-> x_i)
__device__ __forceinline__ float node_eval_q(float4 q0, float4 q1, float4 q2,
                                             float4 q3, float4 xv) {
    float s0 = fmaf(xv.y, fmaf(xv.x, q0.w, q0.z), fmaf(xv.x, q0.y, q0.x));
    float s1 = fmaf(xv.y, fmaf(xv.x, q1.w, q1.z), fmaf(xv.x, q1.y, q1.x));
    float s2 = fmaf(xv.y, fmaf(xv.x, q2.w, q2.z), fmaf(xv.x, q2.y, q2.x));
    float s3 = fmaf(xv.y, fmaf(xv.x, q3.w, q3.z), fmaf(xv.x, q3.y, q3.x));
    return fmaf(xv.w, fmaf(xv.z, s3, s2), fmaf(xv.z, s1, s0));
}

__device__ __forceinline__ void load_batch(float4* B, const float4* xb, int j, int lane) {
    #pragma unroll
    for (int r = 0; r < G; ++r)
        B[r] = xb[r * 256 + j * 32 + lane];
}

__global__ void __launch_bounds__(THREADS, 3) lut_tree_kernel(
    const float* __restrict__ x,
    const float* __restrict__ t0, const float* __restrict__ t1,
    const float* __restrict__ t2, const float* __restrict__ t3,
    const float* __restrict__ t4,
    float* __restrict__ out, int nt)
{
    extern __shared__ __align__(16) float smem[];
    float* sh_t = smem;                 // [341][20] monomial coefs
    float* sh_x = smem + TTOT;          // [NWARPS][G][256] exchange

    // ---- loader: fetch 16 corners per node, Mobius transform, store padded ----
    for (int g = threadIdx.x; g < N_NODES; g += THREADS) {
        const float* src; int ln;
        if (g < 256)      { src = t0; ln = g; }
        else if (g < 320) { src = t1; ln = g - 256; }
        else if (g < 336) { src = t2; ln = g - 320; }
        else if (g < 340) { src = t3; ln = g - 336; }
        else              { src = t4; ln = 0; }
        float v[16];
        #pragma unroll
        for (int k = 0; k < 16; ++k) v[k] = src[ln * 16 + k];
        #pragma unroll
        for (int i = 0; i < 4; ++i)
            #pragma unroll
            for (int c = 0; c < 16; ++c)
                if (c & (1 << i)) v[c] -= v[c ^ (1 << i)];
        float* dst = sh_t + g * NODE_F;
        #pragma unroll
        for (int k = 0; k < 16; ++k) dst[k] = v[k];
    }
    __syncthreads();

    const int warp = threadIdx.x >> 5;
    const int lane = threadIdx.x & 31;
    const unsigned FULL = 0xffffffffu;
    float* xch = sh_x + warp * (G * 256);

    uns t;
    if (lane == 0) t = atomicAdd(&g_ctr, 1);
    t = __shfl_sync(FULL, t, 0);

    float4 B[4][G];                      // ring: read B[j&3], write B[(j+3)&3]
    const float4* xb = (const float4*)x + (size_t)t * (G * 256);
    if (t < (uns)nt) {
        load_batch(B[0], xb, 0, lane);
        load_batch(B[1], xb, 1, lane);
        load_batch(B[2], xb, 2, lane);
    }

    while (t < (uns)nt) {
        uns tn = 0xffffffffu;
        const float4* xbn = xb;

        // ---- layer 0: prefetch distance 3, stream crosses into next tile ----
        #pragma unroll
        for (int j = 0; j < 8; ++j) {
            if (j < 5) {
                load_batch(B[(j + 3) & 3], xb, j + 3, lane);
            } else {
                if (j == 5) {
                    if (lane == 0) tn = atomicAdd(&g_ctr, 1);
                    tn = __shfl_sync(FULL, tn, 0);
                    xbn = (const float4*)x + (size_t)tn * (G * 256);
                }
                if (tn < (uns)nt)
                    load_batch(B[(j + 3) & 3], xbn, j - 5, lane);
            }
            const float* cp = sh_t + (j * 32 + lane) * NODE_F;
            float4 q0 = *(const float4*)(cp + 0);
            float4 q1 = *(const float4*)(cp + 4);
            float4 q2 = *(const float4*)(cp + 8);
            float4 q3 = *(const float4*)(cp + 12);
            #pragma unroll
            for (int r = 0; r < G; ++r)
                xch[r * 256 + j * 32 + lane] =
                    node_eval_q(q0, q1, q2, q3, B[j & 3][r]);
        }
        __syncwarp();

        // ---- layers 1..4, table-outer / rows-inner ----
        float z0[G], z1[G], wv[G], vv[G];

        {   // layer 1, node 2*lane
            const float* cp = sh_t + (256 + 2 * lane) * NODE_F;
            float4 q0 = *(const float4*)(cp + 0), q1 = *(const float4*)(cp + 4);
            float4 q2 = *(const float4*)(cp + 8), q3 = *(const float4*)(cp + 12);
            #pragma unroll
            for (int r = 0; r < G; ++r) {
                float4 a = *(const float4*)&xch[r * 256 + lane * 8];
                z0[r] = node_eval_q(q0, q1, q2, q3, a);
            }
        }
        {   // layer 1, node 2*lane+1
            const float* cp = sh_t + (256 + 2 * lane + 1) * NODE_F;
            float4 q0 = *(const float4*)(cp + 0), q1 = *(const float4*)(cp + 4);
            float4 q2 = *(const float4*)(cp + 8), q3 = *(const float4*)(cp + 12);
            #pragma unroll
            for (int r = 0; r < G; ++r) {
                float4 a = *(const float4*)&xch[r * 256 + lane * 8 + 4];
                z1[r] = node_eval_q(q0, q1, q2, q3, a);
            }
        }
        {   // layer 2, node lane&15
            const float* cp = sh_t + (320 + (lane & 15)) * NODE_F;
            float4 q0 = *(const float4*)(cp + 0), q1 = *(const float4*)(cp + 4);
            float4 q2 = *(const float4*)(cp + 8), q3 = *(const float4*)(cp + 12);
            #pragma unroll
            for (int r = 0; r < G; ++r) {
                float4 b;
                b.x = __shfl_sync(FULL, z0[r], (lane * 2) & 31);
                b.y = __shfl_sync(FULL, z1[r], (lane * 2) & 31);
                b.z = __shfl_sync(FULL, z0[r], (lane * 2 + 1) & 31);
                b.w = __shfl_sync(FULL, z1[r], (lane * 2 + 1) & 31);
                wv[r] = node_eval_q(q0, q1, q2, q3, b);
            }
        }
        {   // layer 3, node lane&3
            const float* cp = sh_t + (336 + (lane & 3)) * NODE_F;
            float4 q0 = *(const float4*)(cp + 0), q1 = *(const float4*)(cp + 4);
            float4 q2 = *(const float4*)(cp + 8), q3 = *(const float4*)(cp + 12);
            #pragma unroll
            for (int r = 0; r < G; ++r) {
                float4 c;
                c.x = __shfl_sync(FULL, wv[r], (lane * 4 + 0) & 31);
                c.y = __shfl_sync(FULL, wv[r], (lane * 4 + 1) & 31);
                c.z = __shfl_sync(FULL, wv[r], (lane * 4 + 2) & 31);
                c.w = __shfl_sync(FULL, wv[r], (lane * 4 + 3) & 31);
                vv[r] = node_eval_q(q0, q1, q2, q3, c);
            }
        }
        {   // layer 4, node 340
            const float* cp = sh_t + 340 * NODE_F;
            float4 q0 = *(const float4*)(cp + 0), q1 = *(const float4*)(cp + 4);
            float4 q2 = *(const float4*)(cp + 8), q3 = *(const float4*)(cp + 12);
            #pragma unroll
            for (int r = 0; r < G; ++r) {
                float4 d;
                d.x = __shfl_sync(FULL, vv[r], 0);
                d.y = __shfl_sync(FULL, vv[r], 1);
                d.z = __shfl_sync(FULL, vv[r], 2);
                d.w = __shfl_sync(FULL, vv[r], 3);
                if (lane == 0)
                    out[t * G + r] = node_eval_q(q0, q1, q2, q3, d);
            }
        }
        __syncwarp();

        t = tn;
        xb = xbn;
    }
}

extern "C" void kernel_launch(void* const* d_in, const int* in_sizes, int n_in,
                              void* d_out, int out_size) {
    const float* x  = (const float*)d_in[0];
    const float* t0 = (const float*)d_in[1];
    const float* t1 = (const float*)d_in[2];
    const float* t2 = (const float*)d_in[3];
    const float* t3 = (const float*)d_in[4];
    const float* t4 = (const float*)d_in[5];
    float* out = (float*)d_out;

    int n_rows = in_sizes[0] / 1024;       // 32768
    int nt = n_rows / G;                   // 16384 tiles

    reset_ctr<<<1, 1>>>();
    cudaFuncSetAttribute(lut_tree_kernel,
                         cudaFuncAttributeMaxDynamicSharedMemorySize, SMEM_B);
    lut_tree_kernel<<<GRID, THREADS, SMEM_B>>>(x, t0, t1, t2, t3, t4, out, nt);
}

// round 14
// speedup vs baseline: 1.1311x; 1.1311x over previous
#include <cuda_runtime.h>

// LUT tree, monomial-coefficient form (R10 base; tail repacked via scratch).
// Loader Mobius-transforms tables -> node eval is 15 pure FMAs.
// Persistent warps steal 4-row tiles; depth-4 register ring prefetches x two
// batches ahead (phase-stable, 8%4==0); next tile stolen at j==6.
// R14: tail layers route through per-warp shared scratch instead of shuffles:
//   L1: 8 evals/lane -> float2 STS        (unchanged math, no registers kept)
//   L2: 2 evals/lane (node lane&15, rows lane>>4 and +2)  [was 4 evals/lane]
//   L3: 1 eval/lane  (node lane&3,  row (lane>>2)&3)      [was 4 evals/lane]
//   L4: 4 lanes, coalesced 16B output store               [was 4 evals/lane]
// All 48 SHFLs deleted; tail instruction count ~470 -> ~220 per warp-tile.

#define THREADS  256
#define NWARPS   8
#define GRID     296            // 2 CTAs/SM * 148 SMs
#define G        4              // rows per tile

#define NODE_F   20             // 16 coefs + 4 pad -> 80B stride, conflict-free
#define N_NODES  341
#define TTOT     (N_NODES * NODE_F)      // 6820 floats
#define XCHF     (NWARPS * G * 256)      // 8192 floats
#define SCRW     336                     // per-warp scratch: 256 + 64 + 16
#define SMEM_B   ((TTOT + XCHF + NWARPS * SCRW) * 4)   // 70800 B

typedef unsigned uns;
__device__ uns g_ctr;
__global__ void reset_ctr() { g_ctr = 0; }

// eval with monomial coefs in registers; index = b0+2b1+4b2+8b3 (bit i <-> x_i)
__device__ __forceinline__ float node_eval_q(float4 q0, float4 q1, float4 q2,
                                             float4 q3, float4 xv) {
    float s0 = fmaf(xv.y, fmaf(xv.x, q0.w, q0.z), fmaf(xv.x, q0.y, q0.x));
    float s1 = fmaf(xv.y, fmaf(xv.x, q1.w, q1.z), fmaf(xv.x, q1.y, q1.x));
    float s2 = fmaf(xv.y, fmaf(xv.x, q2.w, q2.z), fmaf(xv.x, q2.y, q2.x));
    float s3 = fmaf(xv.y, fmaf(xv.x, q3.w, q3.z), fmaf(xv.x, q3.y, q3.x));
    return fmaf(xv.w, fmaf(xv.z, s3, s2), fmaf(xv.z, s1, s0));
}

__device__ __forceinline__ void load_batch(float4* B, const float4* xb, int j, int lane) {
    #pragma unroll
    for (int r = 0; r < G; ++r)
        B[r] = xb[r * 256 + j * 32 + lane];
}

__global__ void __launch_bounds__(THREADS, 2) lut_tree_kernel(
    const float* __restrict__ x,
    const float* __restrict__ t0, const float* __restrict__ t1,
    const float* __restrict__ t2, const float* __restrict__ t3,
    const float* __restrict__ t4,
    float* __restrict__ out, int nt)
{
    extern __shared__ __align__(16) float smem[];
    float* sh_t = smem;                 // [341][20] monomial coefs
    float* sh_x = smem + TTOT;          // [NWARPS][G][256] layer-0 exchange
    float* sh_s = sh_x + XCHF;          // [NWARPS][336] tail scratch

    // ---- loader: fetch 16 corners per node, Mobius transform, store padded ----
    for (int g = threadIdx.x; g < N_NODES; g += THREADS) {
        const float* src; int ln;
        if (g < 256)      { src = t0; ln = g; }
        else if (g < 320) { src = t1; ln = g - 256; }
        else if (g < 336) { src = t2; ln = g - 320; }
        else if (g < 340) { src = t3; ln = g - 336; }
        else              { src = t4; ln = 0; }
        float v[16];
        #pragma unroll
        for (int k = 0; k < 16; ++k) v[k] = src[ln * 16 + k];
        #pragma unroll
        for (int i = 0; i < 4; ++i)
            #pragma unroll
            for (int c = 0; c < 16; ++c)
                if (c & (1 << i)) v[c] -= v[c ^ (1 << i)];
        float* dst = sh_t + g * NODE_F;
        #pragma unroll
        for (int k = 0; k < 16; ++k) dst[k] = v[k];
    }
    __syncthreads();

    const int warp = threadIdx.x >> 5;
    const int lane = threadIdx.x & 31;
    const unsigned FULL = 0xffffffffu;
    float* xch = sh_x + warp * (G * 256);
    float* s1  = sh_s + warp * SCRW;     // [4][64] layer-1 out
    float* s2  = s1 + 256;               // [4][16] layer-2 out
    float* s3  = s2 + 64;                // [16]    layer-3 out

    uns t;
    if (lane == 0) t = atomicAdd(&g_ctr, 1);
    t = __shfl_sync(FULL, t, 0);

    float4 B[4][G];                      // depth-4 ring: read B[j&3], write B[(j+2)&3]
    const float4* xb = (const float4*)x + (size_t)t * (G * 256);
    if (t < (uns)nt) {
        load_batch(B[0], xb, 0, lane);
        load_batch(B[1], xb, 1, lane);
    }

    while (t < (uns)nt) {
        uns tn = 0xffffffffu;
        const float4* xbn = xb;

        // ---- layer 0: prefetch depth 2, stream crosses into next tile ----
        #pragma unroll
        for (int j = 0; j < 8; ++j) {
            if (j < 6) {
                load_batch(B[(j + 2) & 3], xb, j + 2, lane);
            } else {
                if (j == 6) {
                    if (lane == 0) tn = atomicAdd(&g_ctr, 1);
                    tn = __shfl_sync(FULL, tn, 0);
                    xbn = (const float4*)x + (size_t)tn * (G * 256);
                }
                if (tn < (uns)nt)
                    load_batch(B[(j + 2) & 3], xbn, j - 6, lane);
            }
            const float* cp = sh_t + (j * 32 + lane) * NODE_F;
            float4 q0 = *(const float4*)(cp + 0);
            float4 q1 = *(const float4*)(cp + 4);
            float4 q2 = *(const float4*)(cp + 8);
            float4 q3 = *(const float4*)(cp + 12);
            #pragma unroll
            for (int r = 0; r < G; ++r)
                xch[r * 256 + j * 32 + lane] =
                    node_eval_q(q0, q1, q2, q3, B[j & 3][r]);
        }
        __syncwarp();

        // ---- layer 1: nodes 2*lane, 2*lane+1 per row -> float2 to s1 ----
        {
            const float* ca = sh_t + (256 + 2 * lane) * NODE_F;
            float4 a0 = *(const float4*)(ca + 0), a1 = *(const float4*)(ca + 4);
            float4 a2 = *(const float4*)(ca + 8), a3 = *(const float4*)(ca + 12);
            const float* cb = sh_t + (256 + 2 * lane + 1) * NODE_F;
            float4 b0 = *(const float4*)(cb + 0), b1 = *(const float4*)(cb + 4);
            float4 b2 = *(const float4*)(cb + 8), b3 = *(const float4*)(cb + 12);
            #pragma unroll
            for (int r = 0; r < G; ++r) {
                float4 i0 = *(const float4*)&xch[r * 256 + lane * 8];
                float4 i1 = *(const float4*)&xch[r * 256 + lane * 8 + 4];
                float z0 = node_eval_q(a0, a1, a2, a3, i0);
                float z1 = node_eval_q(b0, b1, b2, b3, i1);
                *(float2*)&s1[r * 64 + 2 * lane] = make_float2(z0, z1);
            }
        }
        __syncwarp();

        // ---- layer 2: node lane&15, rows lane>>4 and (lane>>4)+2 ----
        {
            int m = lane & 15, r0 = lane >> 4;
            const float* cp = sh_t + (320 + m) * NODE_F;
            float4 q0 = *(const float4*)(cp + 0), q1 = *(const float4*)(cp + 4);
            float4 q2 = *(const float4*)(cp + 8), q3 = *(const float4*)(cp + 12);
            float4 u0 = *(const float4*)&s1[r0 * 64 + 4 * m];
            float4 u1 = *(const float4*)&s1[(r0 + 2) * 64 + 4 * m];
            s2[r0 * 16 + m]       = node_eval_q(q0, q1, q2, q3, u0);
            s2[(r0 + 2) * 16 + m] = node_eval_q(q0, q1, q2, q3, u1);
        }
        __syncwarp();

        // ---- layer 3: node lane&3, row (lane>>2)&3 (lanes 16-31 duplicate) ----
        {
            int qn = lane & 3, rr = (lane >> 2) & 3;
            const float* cp = sh_t + (336 + qn) * NODE_F;
            float4 q0 = *(const float4*)(cp + 0), q1 = *(const float4*)(cp + 4);
            float4 q2 = *(const float4*)(cp + 8), q3 = *(const float4*)(cp + 12);
            float4 u = *(const float4*)&s2[rr * 16 + 4 * qn];
            float v = node_eval_q(q0, q1, q2, q3, u);
            if (lane < 16) s3[rr * 4 + qn] = v;
        }
        __syncwarp();

        // ---- layer 4: lanes 0-3, row lane; coalesced 16B output store ----
        {
            const float* cp = sh_t + 340 * NODE_F;
            float4 q0 = *(const float4*)(cp + 0), q1 = *(const float4*)(cp + 4);
            float4 q2 = *(const float4*)(cp + 8), q3 = *(const float4*)(cp + 12);
            if (lane < 4) {
                float4 d = *(const float4*)&s3[lane * 4];
                out[t * G + lane] = node_eval_q(q0, q1, q2, q3, d);
            }
        }
        __syncwarp();

        t = tn;
        xb = xbn;
    }
}

extern "C" void kernel_launch(void* const* d_in, const int* in_sizes, int n_in,
                              void* d_out, int out_size) {
    const float* x  = (const float*)d_in[0];
    const float* t0 = (const float*)d_in[1];
    const float* t1 = (const float*)d_in[2];
    const float* t2 = (const float*)d_in[3];
    const float* t3 = (const float*)d_in[4];
    const float* t4 = (const float*)d_in[5];
    float* out = (float*)d_out;

    int n_rows = in_sizes[0] / 1024;       // 32768
    int nt = n_rows / G;                   // 8192 tiles

    reset_ctr<<<1, 1>>>();
    cudaFuncSetAttribute(lut_tree_kernel,
                         cudaFuncAttributeMaxDynamicSharedMemorySize, SMEM_B);
    lut_tree_kernel<<<GRID, THREADS, SMEM_B>>>(x, t0, t1, t2, t3, t4, out, nt);
}

// round 15
// speedup vs baseline: 1.1570x; 1.0229x over previous
#include <cuda_runtime.h>

// LUT tree, monomial-coefficient form (R14 base + streaming x loads + distance-3).
// Loader Mobius-transforms tables -> node eval is 15 pure FMAs.
// Persistent warps steal 4-row tiles; depth-4 register ring prefetches x THREE
// batches ahead (read slot j&3, write slot (j+3)&3; phase stable, 8%4==0).
// x loads use __ldcs (LDG.128.CS evict-first) — x is streamed once, keep it out
// of L1/L2 residency. Next tile stolen at j==5; its batches 0..2 load under
// j=5..7 and the tail. Tail layers repacked through per-warp shared scratch
// (no shuffles): L1 8 evals/lane, L2 2, L3 1, L4 lanes 0-3.

#define THREADS  256
#define NWARPS   8
#define GRID     296            // 2 CTAs/SM * 148 SMs
#define G        4              // rows per tile

#define NODE_F   20             // 16 coefs + 4 pad -> 80B stride, conflict-free
#define N_NODES  341
#define TTOT     (N_NODES * NODE_F)      // 6820 floats
#define XCHF     (NWARPS * G * 256)      // 8192 floats
#define SCRW     336                     // per-warp scratch: 256 + 64 + 16
#define SMEM_B   ((TTOT + XCHF + NWARPS * SCRW) * 4)   // 70800 B

typedef unsigned uns;
__device__ uns g_ctr;
__global__ void reset_ctr() { g_ctr = 0; }

// eval with monomial coefs in registers; index = b0+2b1+4b2+8b3 (bit i <-> x_i)
__device__ __forceinline__ float node_eval_q(float4 q0, float4 q1, float4 q2,
                                             float4 q3, float4 xv) {
    float s0 = fmaf(xv.y, fmaf(xv.x, q0.w, q0.z), fmaf(xv.x, q0.y, q0.x));
    float s1 = fmaf(xv.y, fmaf(xv.x, q1.w, q1.z), fmaf(xv.x, q1.y, q1.x));
    float s2 = fmaf(xv.y, fmaf(xv.x, q2.w, q2.z), fmaf(xv.x, q2.y, q2.x));
    float s3 = fmaf(xv.y, fmaf(xv.x, q3.w, q3.z), fmaf(xv.x, q3.y, q3.x));
    return fmaf(xv.w, fmaf(xv.z, s3, s2), fmaf(xv.z, s1, s0));
}

// streaming (evict-first) batch load
__device__ __forceinline__ void load_batch(float4* B, const float4* xb, int j, int lane) {
    #pragma unroll
    for (int r = 0; r < G; ++r)
        B[r] = __ldcs(&xb[r * 256 + j * 32 + lane]);
}

__global__ void __launch_bounds__(THREADS, 2) lut_tree_kernel(
    const float* __restrict__ x,
    const float* __restrict__ t0, const float* __restrict__ t1,
    const float* __restrict__ t2, const float* __restrict__ t3,
    const float* __restrict__ t4,
    float* __restrict__ out, int nt)
{
    extern __shared__ __align__(16) float smem[];
    float* sh_t = smem;                 // [341][20] monomial coefs
    float* sh_x = smem + TTOT;          // [NWARPS][G][256] layer-0 exchange
    float* sh_s = sh_x + XCHF;          // [NWARPS][336] tail scratch

    // ---- loader: fetch 16 corners per node, Mobius transform, store padded ----
    for (int g = threadIdx.x; g < N_NODES; g += THREADS) {
        const float* src; int ln;
        if (g < 256)      { src = t0; ln = g; }
        else if (g < 320) { src = t1; ln = g - 256; }
        else if (g < 336) { src = t2; ln = g - 320; }
        else if (g < 340) { src = t3; ln = g - 336; }
        else              { src = t4; ln = 0; }
        float v[16];
        #pragma unroll
        for (int k = 0; k < 16; ++k) v[k] = src[ln * 16 + k];
        #pragma unroll
        for (int i = 0; i < 4; ++i)
            #pragma unroll
            for (int c = 0; c < 16; ++c)
                if (c & (1 << i)) v[c] -= v[c ^ (1 << i)];
        float* dst = sh_t + g * NODE_F;
        #pragma unroll
        for (int k = 0; k < 16; ++k) dst[k] = v[k];
    }
    __syncthreads();

    const int warp = threadIdx.x >> 5;
    const int lane = threadIdx.x & 31;
    const unsigned FULL = 0xffffffffu;
    float* xch = sh_x + warp * (G * 256);
    float* s1  = sh_s + warp * SCRW;     // [4][64] layer-1 out
    float* s2  = s1 + 256;               // [4][16] layer-2 out
    float* s3  = s2 + 64;                // [16]    layer-3 out

    uns t;
    if (lane == 0) t = atomicAdd(&g_ctr, 1);
    t = __shfl_sync(FULL, t, 0);

    float4 B[4][G];                      // ring: read B[j&3], write B[(j+3)&3]
    const float4* xb = (const float4*)x + (size_t)t * (G * 256);
    if (t < (uns)nt) {
        load_batch(B[0], xb, 0, lane);
        load_batch(B[1], xb, 1, lane);
        load_batch(B[2], xb, 2, lane);
    }

    while (t < (uns)nt) {
        uns tn = 0xffffffffu;
        const float4* xbn = xb;

        // ---- layer 0: prefetch distance 3, stream crosses into next tile ----
        #pragma unroll
        for (int j = 0; j < 8; ++j) {
            if (j < 5) {
                load_batch(B[(j + 3) & 3], xb, j + 3, lane);
            } else {
                if (j == 5) {
                    if (lane == 0) tn = atomicAdd(&g_ctr, 1);
                    tn = __shfl_sync(FULL, tn, 0);
                    xbn = (const float4*)x + (size_t)tn * (G * 256);
                }
                if (tn < (uns)nt)
                    load_batch(B[(j + 3) & 3], xbn, j - 5, lane);
            }
            const float* cp = sh_t + (j * 32 + lane) * NODE_F;
            float4 q0 = *(const float4*)(cp + 0);
            float4 q1 = *(const float4*)(cp + 4);
            float4 q2 = *(const float4*)(cp + 8);
            float4 q3 = *(const float4*)(cp + 12);
            #pragma unroll
            for (int r = 0; r < G; ++r)
                xch[r * 256 + j * 32 + lane] =
                    node_eval_q(q0, q1, q2, q3, B[j & 3][r]);
        }
        __syncwarp();

        // ---- layer 1: nodes 2*lane, 2*lane+1 per row -> float2 to s1 ----
        {
            const float* ca = sh_t + (256 + 2 * lane) * NODE_F;
            float4 a0 = *(const float4*)(ca + 0), a1 = *(const float4*)(ca + 4);
            float4 a2 = *(const float4*)(ca + 8), a3 = *(const float4*)(ca + 12);
            const float* cb = sh_t + (256 + 2 * lane + 1) * NODE_F;
            float4 b0 = *(const float4*)(cb + 0), b1 = *(const float4*)(cb + 4);
            float4 b2 = *(const float4*)(cb + 8), b3 = *(const float4*)(cb + 12);
            #pragma unroll
            for (int r = 0; r < G; ++r) {
                float4 i0 = *(const float4*)&xch[r * 256 + lane * 8];
                float4 i1 = *(const float4*)&xch[r * 256 + lane * 8 + 4];
                float z0 = node_eval_q(a0, a1, a2, a3, i0);
                float z1 = node_eval_q(b0, b1, b2, b3, i1);
                *(float2*)&s1[r * 64 + 2 * lane] = make_float2(z0, z1);
            }
        }
        __syncwarp();

        // ---- layer 2: node lane&15, rows lane>>4 and (lane>>4)+2 ----
        {
            int m = lane & 15, r0 = lane >> 4;
            const float* cp = sh_t + (320 + m) * NODE_F;
            float4 q0 = *(const float4*)(cp + 0), q1 = *(const float4*)(cp + 4);
            float4 q2 = *(const float4*)(cp + 8), q3 = *(const float4*)(cp + 12);
            float4 u0 = *(const float4*)&s1[r0 * 64 + 4 * m];
            float4 u1 = *(const float4*)&s1[(r0 + 2) * 64 + 4 * m];
            s2[r0 * 16 + m]       = node_eval_q(q0, q1, q2, q3, u0);
            s2[(r0 + 2) * 16 + m] = node_eval_q(q0, q1, q2, q3, u1);
        }
        __syncwarp();

        // ---- layer 3: node lane&3, row (lane>>2)&3 (lanes 16-31 duplicate) ----
        {
            int qn = lane & 3, rr = (lane >> 2) & 3;
            const float* cp = sh_t + (336 + qn) * NODE_F;
            float4 q0 = *(const float4*)(cp + 0), q1 = *(const float4*)(cp + 4);
            float4 q2 = *(const float4*)(cp + 8), q3 = *(const float4*)(cp + 12);
            float4 u = *(const float4*)&s2[rr * 16 + 4 * qn];
            float v = node_eval_q(q0, q1, q2, q3, u);
            if (lane < 16) s3[rr * 4 + qn] = v;
        }
        __syncwarp();

        // ---- layer 4: lanes 0-3, row lane; output store ----
        {
            const float* cp = sh_t + 340 * NODE_F;
            float4 q0 = *(const float4*)(cp + 0), q1 = *(const float4*)(cp + 4);
            float4 q2 = *(const float4*)(cp + 8), q3 = *(const float4*)(cp + 12);
            if (lane < 4) {
                float4 d = *(const float4*)&s3[lane * 4];
                out[t * G + lane] = node_eval_q(q0, q1, q2, q3, d);
            }
        }
        __syncwarp();

        t = tn;
        xb = xbn;
    }
}

extern "C" void kernel_launch(void* const* d_in, const int* in_sizes, int n_in,
                              void* d_out, int out_size) {
    const float* x  = (const float*)d_in[0];
    const float* t0 = (const float*)d_in[1];
    const float* t1 = (const float*)d_in[2];
    const float* t2 = (const float*)d_in[3];
    const float* t3 = (const float*)d_in[4];
    const float* t4 = (const float*)d_in[5];
    float* out = (float*)d_out;

    int n_rows = in_sizes[0] / 1024;       // 32768
    int nt = n_rows / G;                   // 8192 tiles

    reset_ctr<<<1, 1>>>();
    cudaFuncSetAttribute(lut_tree_kernel,
                         cudaFuncAttributeMaxDynamicSharedMemorySize, SMEM_B);
    lut_tree_kernel<<<GRID, THREADS, SMEM_B>>>(x, t0, t1, t2, t3, t4, out, nt);
}